// round 16
// baseline (speedup 1.0000x reference)
#include <cuda_runtime.h>
#include <math.h>

#define Nn 4096
#define Kn 16
#define K1 17
#define Tt 16
#define NTt 16
#define Dd 128
#define TTe 256
#define PINV (1.0f/17.0f)
#define TINYF 1e-16f
#define NPREP 257

// ---- device globals (static, no runtime allocation) ----
__device__ float g_q[TTe];      // softmax(q0)
__device__ float g_cq2[TTe];    // sum_m q[t,m]*C2[t,l,m]^2
__device__ float g_qc2[TTe];    // sum_m q[t,m]*C2[t,l,m]
__device__ float g_alpha[2];    // alpha, 1-alpha
__device__ float g_XT[Nn*TTe];  // XT[n][tm] = ||x_n||^2 + ||tf_tm||^2 - 2<x_n,tf_tm>
__device__ int   g_done = 0;    // prep-completion counter (self-resetting)
__device__ int   g_pass = 0;    // blocks-past-wait counter (self-resetting)

// smem layout for the OT phase (float offsets)
#define NB_O   0     // 17 int
#define RB_O   17    // 17 int (row bitmasks)
#define T1_O   36    // 17 float: raw popcount cnt[k]
#define M_O    64    // 16 * 272
#define KG_O   4416  // 16 * 272   Kt (swizzled) then aliased by G[k*16+m]
#define H_O    8768  // 16 * 272   H[j*16+l]
#define V_O    13120 // 16 * 16
#define SM_FLOATS 13376
// GEMM phase needs 2*64*33 float4 + 128 floats = 68096 B (larger; same extern smem)
#define SM_BYTES (2*64*33*16 + 128*4)

__global__ __launch_bounds__(512, 2)
void ltfgw_kernel(const float* __restrict__ x,
                  const float* __restrict__ tf,
                  const float* __restrict__ q0,
                  const float* __restrict__ alpha0,
                  const float* __restrict__ adj,
                  const int*   __restrict__ nbr,
                  const float* __restrict__ tmpl,
                  float* __restrict__ out) {
    extern __shared__ float smf[];
    const int n    = blockIdx.x;
    const int tid  = threadIdx.x;
    const int lane = tid & 31;
    const int t    = tid >> 5;
    const int l    = lane & 15;
    const int h    = lane >> 4;

    // ================= prep role: blocks 0..255 GEMM tile, block 256 setup =================
    if (n < NPREP) {
        if (n == 256) {
            // ---- scalar setup ----
            float* qs = smf;   // 256 floats
            if (tid == 0) {
                float a = 1.0f / (1.0f + expf(-alpha0[0]));
                g_alpha[0] = a; g_alpha[1] = 1.0f - a;
            }
            if (tid < Tt) {
                float mx = -3.402823466e38f;
                for (int m = 0; m < NTt; m++) mx = fmaxf(mx, q0[tid*NTt+m]);
                float e[NTt]; float s = 0.0f;
                for (int m = 0; m < NTt; m++) { e[m] = expf(q0[tid*NTt+m] - mx); s += e[m]; }
                float inv = 1.0f / s;
                for (int m = 0; m < NTt; m++) { float v = e[m]*inv; qs[tid*NTt+m] = v; g_q[tid*NTt+m] = v; }
            }
            __syncthreads();
            if (tid < TTe) {
                int tt = tid >> 4;
                float s = 0.0f, s3 = 0.0f;
                const float4* c4 = (const float4*)(tmpl + tid*NTt);
                #pragma unroll
                for (int i = 0; i < 4; i++) {
                    float4 c = c4[i];
                    const float* qq = qs + tt*NTt + 4*i;
                    s  += qq[0]*c.x*c.x + qq[1]*c.y*c.y + qq[2]*c.z*c.z + qq[3]*c.w*c.w;
                    s3 += qq[0]*c.x     + qq[1]*c.y     + qq[2]*c.z     + qq[3]*c.w;
                }
                g_cq2[tid] = s;
                g_qc2[tid] = s3;
            }
        } else {
            // ---- 64x64 XT GEMM tile ----
            float4* xs = (float4*)smf;            // 64 x 33
            float4* ts = xs + 64*33;              // 64 x 33
            float*  xn2 = (float*)(ts + 64*33);   // 64
            float*  tn2 = xn2 + 64;               // 64
            int n0 = (n & 63)*64, m0 = (n >> 6)*64;
            const float4* xg = (const float4*)(x + (size_t)n0*Dd);
            const float4* tg = (const float4*)(tf + (size_t)m0*Dd);
            for (int i = tid; i < 64*32; i += 512) {
                int r = i >> 5, c = i & 31;
                xs[r*33+c] = xg[r*32+c];
                ts[r*33+c] = tg[r*32+c];
            }
            __syncthreads();
            if (tid < 128) {
                int r = tid & 63;
                const float4* src = (tid < 64) ? (xs + r*33) : (ts + r*33);
                float s = 0.0f;
                #pragma unroll 8
                for (int c = 0; c < 32; c++) {
                    float4 v = src[c];
                    s += v.x*v.x + v.y*v.y + v.z*v.z + v.w*v.w;
                }
                if (tid < 64) xn2[r] = s; else tn2[r] = s;
            }
            __syncthreads();
            int tx = tid & 31, ty = tid >> 5;   // tx -> 2 m cols, ty -> 4 n rows
            float acc[4][2];
            #pragma unroll
            for (int i = 0; i < 4; i++) { acc[i][0] = 0.0f; acc[i][1] = 0.0f; }
            #pragma unroll 4
            for (int k = 0; k < 32; k++) {
                float4 a[4], b[2];
                #pragma unroll
                for (int i = 0; i < 4; i++) a[i] = xs[(ty*4+i)*33 + k];
                #pragma unroll
                for (int j = 0; j < 2; j++) b[j] = ts[(tx*2+j)*33 + k];
                #pragma unroll
                for (int i = 0; i < 4; i++)
                    #pragma unroll
                    for (int j = 0; j < 2; j++)
                        acc[i][j] = fmaf(a[i].x, b[j].x, fmaf(a[i].y, b[j].y,
                                     fmaf(a[i].z, b[j].z, fmaf(a[i].w, b[j].w, acc[i][j]))));
            }
            float t0 = tn2[tx*2+0], t1v = tn2[tx*2+1];
            #pragma unroll
            for (int i = 0; i < 4; i++) {
                int nn = n0 + ty*4 + i;
                float xn = xn2[ty*4+i];
                float2 o;
                o.x = xn + t0  - 2.0f*acc[i][0];
                o.y = xn + t1v - 2.0f*acc[i][1];
                *(float2*)(g_XT + (size_t)nn*TTe + m0 + tx*2) = o;
            }
        }
        __threadfence();
        __syncthreads();
        if (tid == 0) atomicAdd(&g_done, 1);
        __syncthreads();   // smem now reusable for OT phase
    }

    // ================= OT phase (all blocks) =================
    int*   nb  = (int*)(smf + NB_O);
    int*   rbs = (int*)(smf + RB_O);
    float* t1f = smf + T1_O;
    float* Mw  = smf + M_O  + t*272;
    float* KGw = smf + KG_O + t*272;   // Kt (swizzled float4 rows), later G
    float* Hw  = smf + H_O  + t*272;
    float* vsm = smf + V_O  + t*16;

    // ---- Phase A1: neighbor list (prep-independent) ----
    if (tid < K1) nb[tid] = (tid == 0) ? n : nbr[n*Kn + tid - 1];
    __syncthreads();

    // ---- Phase A3: row bitmasks of binary 17x17 C1 (prep-independent) ----
    {
        const float* arow = adj + (size_t)nb[t]*Nn;
        float v = (lane < K1) ? arow[nb[lane]] : 0.0f;
        unsigned bits = __ballot_sync(0xffffffffu, v != 0.0f);
        if (lane == 0) {
            rbs[t] = (int)bits;
            t1f[t] = (float)__popc(bits);   // raw count; alpha folded later
        }
        if (t == 0) {
            const float* arow2 = adj + (size_t)nb[16]*Nn;
            float v2 = (lane < K1) ? arow2[nb[lane]] : 0.0f;
            unsigned bits2 = __ballot_sync(0xffffffffu, v2 != 0.0f);
            if (lane == 0) {
                rbs[16] = (int)bits2;
                t1f[16] = (float)__popc(bits2);
            }
        }
    }

    // ---- wait for prep completion (blocks 0..256 are wave-1 resident: 257 <= 296) ----
    if (tid == 0) {
        volatile int* dp = &g_done;
        while (*dp < NPREP) { __nanosleep(100); }
        __threadfence();
        int p = atomicAdd(&g_pass, 1);
        if (p == Nn - 1) {             // last block past the gate: reset for next replay
            atomicExch(&g_done, 0);
            atomicExch(&g_pass, 0);
        }
    }
    __syncthreads();

    // ---- Phase A2: M gather (per warp, LDG from precomputed XT) ----
    #pragma unroll
    for (int ii = 0; ii < 9; ii++) {
        int e = lane + 32*ii;
        if (e < 272) {
            int k = e >> 4;
            Mw[e] = __ldg(&g_XT[(size_t)nb[k]*TTe + t*16 + (e & 15)]);
        }
    }
    __syncthreads();   // publish rbs/t1f across warps

    const float alpha = g_alpha[0];
    const float oneMa = g_alpha[1];
    const float twoA  = 2.0f*alpha;
    const float apc   = alpha * PINV;

    // each warp derives the union mask locally
    unsigned rb_l = (lane < K1) ? (unsigned)rbs[lane] : 0u;
    const unsigned UB = __ballot_sync(0xffffffffu, rb_l != 0u);
    const int lastOuter = (UB == 0u) ? 1 : 3;

    const float qreg   = __ldg(&g_q[t*16 + l]);
    const float ac     = alpha * __ldg(&g_cq2[t*16 + l]);
    const float lanec2 = apc * (-2.0f * __ldg(&g_qc2[t*16 + l]));  // apc*(lanec-1)

    // ---- fold affine constants into M once: Mb = oneMa*M + ac + apc*cnt[k] ----
    #pragma unroll
    for (int ii = 0; ii < 9; ii++) {
        int e = lane + 32*ii;
        if (e < 272) {
            int k = e >> 4;
            Mw[e] = fmaf(oneMa, Mw[e], fmaf(apc, t1f[k], ac));
        }
    }
    __syncwarp();

    float karr[9];   // K parity layout: karr[ii] = K[2ii+h][l]
    float urow[9];   // urow[ii] = u_{2ii+h}
    float vreg = 1.0f;
    const int swz = (lane >> 1) & 3;   // Kt row-load swizzle for lane==k

    for (int outer = 0; ; outer++) {
        float ge[9];
        // ---------- grad ----------
        if (outer == 0 || UB == 0u) {
            // analytic H0: ge = Mb + cnt[k]*apc*(lanec-1)
            #pragma unroll
            for (int ii = 0; ii < 9; ii++) {
                int e = lane + 32*ii;
                ge[ii] = (e < 272) ? fmaf(t1f[e >> 4], lanec2, Mw[e]) : 0.0f;
            }
        } else {
            #pragma unroll
            for (int ii = 0; ii < 9; ii++) {
                int e = lane + 32*ii;
                if (e < 272) {
                    int k = e >> 4;
                    int bits = rbs[k];
                    float s = 0.0f;
                    while (bits) {
                        int j = __ffs(bits) - 1;
                        bits &= bits - 1;
                        s += Hw[j*16 + l];
                    }
                    ge[ii] = fmaf(-twoA, s, Mw[e]);
                } else ge[ii] = 0.0f;
            }
        }

        if (outer == lastOuter) {
            float acc = 0.0f;
            #pragma unroll
            for (int ii = 0; ii < 9; ii++)
                acc = fmaf(ge[ii], karr[ii]*urow[ii]*vreg, acc);
            #pragma unroll
            for (int s2 = 16; s2 > 0; s2 >>= 1)
                acc += __shfl_xor_sync(0xffffffffu, acc, s2);
            if (lane == 0) out[n*Tt + t] = acc;
            break;
        }

        // ---------- eps ----------
        float mn = ge[0], mx = ge[0];
        #pragma unroll
        for (int ii = 1; ii < 8; ii++) { mn = fminf(mn, ge[ii]); mx = fmaxf(mx, ge[ii]); }
        if (lane < 16) { mn = fminf(mn, ge[8]); mx = fmaxf(mx, ge[8]); }
        #pragma unroll
        for (int s2 = 16; s2 > 0; s2 >>= 1) {
            mn = fminf(mn, __shfl_xor_sync(0xffffffffu, mn, s2));
            mx = fmaxf(mx, __shfl_xor_sync(0xffffffffu, mx, s2));
        }
        float inv_eps = __fdividef(1.0f, 0.1f*(mx - mn) + TINYF);

        // ---------- K = exp; store swizzled Kt ----------
        #pragma unroll
        for (int ii = 0; ii < 9; ii++) {
            int e = lane + 32*ii;
            if (e < 272) {
                float kv = __expf((mn - ge[ii]) * inv_eps);
                karr[ii] = kv;
                int k = 2*ii + h;
                KGw[k*16 + (((l>>2) ^ (ii&3))<<2) + (l&3)] = kv;
            } else karr[ii] = 0.0f;
        }
        __syncwarp();

        // ---------- load my row k=lane into registers (once per outer) ----------
        float4 kr0, kr1, kr2, kr3;
        if (lane < K1) {
            const float4* kt4 = (const float4*)KGw;
            kr0 = kt4[lane*4 + (0^swz)];
            kr1 = kt4[lane*4 + (1^swz)];
            kr2 = kt4[lane*4 + (2^swz)];
            kr3 = kt4[lane*4 + (3^swz)];
        } else {
            kr0 = kr1 = kr2 = kr3 = make_float4(0.f,0.f,0.f,0.f);
        }
        __syncwarp();   // Kt region free for G after this

        // ---------- Sinkhorn (proven register/smem form) ----------
        float u;
        {
            float s0 = (kr0.x + kr0.y) + (kr0.z + kr0.w);
            float s1 = (kr1.x + kr1.y) + (kr1.z + kr1.w);
            float s2 = (kr2.x + kr2.y) + (kr2.z + kr2.w);
            float s3 = (kr3.x + kr3.y) + (kr3.z + kr3.w);
            float S  = (s0 + s1) + (s2 + s3);
            if (lane >= K1) S = 1.0f;
            u = __fdividef(PINV, fmaxf(S, TINYF));
        }
        #pragma unroll
        for (int it = 0; it < 5; it++) {
            // gather u into parity layout
            #pragma unroll
            for (int ii = 0; ii < 9; ii++)
                urow[ii] = __shfl_sync(0xffffffffu, u, 2*ii + h);
            // v-step: 3-accumulator column partials + xor16
            float a0 = karr[0]*urow[0];
            float a1 = karr[1]*urow[1];
            float a2 = karr[2]*urow[2];
            a0 = fmaf(karr[3], urow[3], a0);
            a1 = fmaf(karr[4], urow[4], a1);
            a2 = fmaf(karr[5], urow[5], a2);
            a0 = fmaf(karr[6], urow[6], a0);
            a1 = fmaf(karr[7], urow[7], a1);
            a2 = fmaf(karr[8], urow[8], a2);
            float sv = (a0 + a1) + a2;
            sv += __shfl_xor_sync(0xffffffffu, sv, 16);
            vreg = __fdividef(qreg, fmaxf(sv, TINYF));
            if (it == 4) break;
            // publish v to smem, register-local u-step (row regs x v broadcast)
            if (lane < 16) vsm[lane] = vreg;
            __syncwarp();
            {
                const float4* vv4 = (const float4*)vsm;
                float4 v0 = vv4[0], v1 = vv4[1], v2 = vv4[2], v3 = vv4[3];
                float b0 = kr0.x*v0.x, b1 = kr0.y*v0.y, b2 = kr0.z*v0.z, b3 = kr0.w*v0.w;
                b0 = fmaf(kr1.x, v1.x, b0); b1 = fmaf(kr1.y, v1.y, b1);
                b2 = fmaf(kr1.z, v1.z, b2); b3 = fmaf(kr1.w, v1.w, b3);
                b0 = fmaf(kr2.x, v2.x, b0); b1 = fmaf(kr2.y, v2.y, b1);
                b2 = fmaf(kr2.z, v2.z, b2); b3 = fmaf(kr2.w, v2.w, b3);
                b0 = fmaf(kr3.x, v3.x, b0); b1 = fmaf(kr3.y, v3.y, b1);
                b2 = fmaf(kr3.z, v3.z, b2); b3 = fmaf(kr3.w, v3.w, b3);
                float S = (b0 + b1) + (b2 + b3);
                if (lane >= K1) S = 1.0f;
                u = __fdividef(PINV, fmaxf(S, TINYF));
            }
        }

        // ---------- G to smem (aliases Kt) + H build (half-warp j pairs) ----------
        if (UB) {
            #pragma unroll
            for (int ii = 0; ii < 9; ii++) {
                int e = lane + 32*ii;
                if (e < 272) KGw[e] = karr[ii]*urow[ii]*vreg;  // conflict-free
            }
            __syncwarp();
            const float4* tp = (const float4*)(tmpl + (t*16 + l)*16);
            float4 c0 = __ldg(tp+0), c1 = __ldg(tp+1), c2 = __ldg(tp+2), c3 = __ldg(tp+3);
            unsigned ub = UB;
            while (ub) {
                int j0 = __ffs(ub) - 1; ub &= ub - 1u;
                int j1 = j0;
                bool have2 = (ub != 0u);
                if (have2) { j1 = __ffs(ub) - 1; ub &= ub - 1u; }
                int j = h ? j1 : j0;               // halves handle different rows
                const float4* gr = (const float4*)(KGw + j*16);
                float4 a = gr[0], b = gr[1], c = gr[2], d = gr[3];
                float p0 = a.x*c0.x, p1 = a.y*c0.y, p2 = a.z*c0.z, p3 = a.w*c0.w;
                p0 = fmaf(b.x, c1.x, p0); p1 = fmaf(b.y, c1.y, p1);
                p2 = fmaf(b.z, c1.z, p2); p3 = fmaf(b.w, c1.w, p3);
                p0 = fmaf(c.x, c2.x, p0); p1 = fmaf(c.y, c2.y, p1);
                p2 = fmaf(c.z, c2.z, p2); p3 = fmaf(c.w, c2.w, p3);
                p0 = fmaf(d.x, c3.x, p0); p1 = fmaf(d.y, c3.y, p1);
                p2 = fmaf(d.z, c3.z, p2); p3 = fmaf(d.w, c3.w, p3);
                float s = (p0 + p1) + (p2 + p3);
                if (h == 0 || have2) Hw[j*16 + l] = s;   // both halves write their row
            }
            __syncwarp();
        }
    }
}

extern "C" void kernel_launch(void* const* d_in, const int* in_sizes, int n_in,
                              void* d_out, int out_size) {
    const float* x    = (const float*)d_in[0];
    const float* adj  = (const float*)d_in[1];
    const int*   nbr  = (const int*)  d_in[2];
    const float* tmpl = (const float*)d_in[3];
    const float* tf   = (const float*)d_in[4];
    const float* q0   = (const float*)d_in[5];
    const float* a0   = (const float*)d_in[6];
    float* out = (float*)d_out;

    cudaFuncSetAttribute(ltfgw_kernel, cudaFuncAttributeMaxDynamicSharedMemorySize, SM_BYTES);

    ltfgw_kernel<<<Nn, 512, SM_BYTES>>>(x, tf, q0, a0, adj, nbr, tmpl, out);
    (void)in_sizes; (void)n_in; (void)out_size;
}

// round 17
// speedup vs baseline: 1.0520x; 1.0520x over previous
#include <cuda_runtime.h>
#include <math.h>

#define Nn 4096
#define Kn 16
#define K1 17
#define Tt 16
#define NTt 16
#define Dd 128
#define TTe 256
#define PINV (1.0f/17.0f)
#define TINYF 1e-16f

// ---- device globals (static, no runtime allocation) ----
__device__ float g_q[TTe];      // softmax(q0)
__device__ float g_cq2[TTe];    // sum_m q[t,m]*C2[t,l,m]^2
__device__ float g_qc2[TTe];    // sum_m q[t,m]*C2[t,l,m]
__device__ float g_alpha[2];    // alpha, 1-alpha
__device__ float g_XT[Nn*TTe];  // XT[n][tm] = ||x_n||^2 + ||tf_tm||^2 - 2<x_n,tf_tm>

// ---- integer warp redux (supported on sm_103a; f32 variant is NOT) ----
__device__ __forceinline__ int redux_min_s32(int v) {
    int r; asm("redux.sync.min.s32 %0,%1,0xffffffff;" : "=r"(r) : "r"(v)); return r;
}
__device__ __forceinline__ int redux_max_s32(int v) {
    int r; asm("redux.sync.max.s32 %0,%1,0xffffffff;" : "=r"(r) : "r"(v)); return r;
}
// order-preserving float<->s32 key (exact bijection for finite floats)
__device__ __forceinline__ int f2key(float f) {
    int i = __float_as_int(f); return i ^ ((i >> 31) & 0x7fffffff);
}
__device__ __forceinline__ float key2f(int i) {
    return __int_as_float(i ^ ((i >> 31) & 0x7fffffff));
}

// ========= fused: XT GEMM (blocks 0..127, 128x64 tiles) + setup (block 128) =========
#define GSM_BYTES ((128+64)*33*16 + (128+64)*4)
__global__ __launch_bounds__(256)
void prep_kernel(const float* __restrict__ x, const float* __restrict__ tf,
                 const float* __restrict__ q0, const float* __restrict__ tmpl,
                 const float* __restrict__ alpha0) {
    extern __shared__ float4 gsm[];
    int tid = threadIdx.x;
    int bx = blockIdx.x;

    if (bx == 128) {
        // ---------------- setup branch ----------------
        float* qs = (float*)gsm;   // 256 floats
        if (tid == 0) {
            float a = 1.0f / (1.0f + expf(-alpha0[0]));
            g_alpha[0] = a; g_alpha[1] = 1.0f - a;
        }
        if (tid < Tt) {
            float mx = -3.402823466e38f;
            for (int m = 0; m < NTt; m++) mx = fmaxf(mx, q0[tid*NTt+m]);
            float e[NTt]; float s = 0.0f;
            for (int m = 0; m < NTt; m++) { e[m] = expf(q0[tid*NTt+m] - mx); s += e[m]; }
            float inv = 1.0f / s;
            for (int m = 0; m < NTt; m++) { float v = e[m]*inv; qs[tid*NTt+m] = v; g_q[tid*NTt+m] = v; }
        }
        __syncthreads();
        if (tid < TTe) {
            int t = tid >> 4;
            float s = 0.0f, s3 = 0.0f;
            const float4* c4 = (const float4*)(tmpl + tid*NTt);
            #pragma unroll
            for (int i = 0; i < 4; i++) {
                float4 c = c4[i];
                const float* qq = qs + t*NTt + 4*i;
                s  += qq[0]*c.x*c.x + qq[1]*c.y*c.y + qq[2]*c.z*c.z + qq[3]*c.w*c.w;
                s3 += qq[0]*c.x     + qq[1]*c.y     + qq[2]*c.z     + qq[3]*c.w;
            }
            g_cq2[tid] = s;
            g_qc2[tid] = s3;
        }
        return;
    }

    // ---------------- GEMM branch: 128(n) x 64(m) tile ----------------
    float4* xs = gsm;                // 128 x 33
    float4* ts = gsm + 128*33;       // 64 x 33
    float*  xn2 = (float*)(gsm + 128*33 + 64*33);  // 128
    float*  tn2 = xn2 + 128;                        // 64
    int n0 = (bx & 31)*128, m0 = (bx >> 5)*64;
    const float4* xg = (const float4*)(x + (size_t)n0*Dd);
    const float4* tg = (const float4*)(tf + (size_t)m0*Dd);
    for (int i = tid; i < 128*32; i += 256) {
        int r = i >> 5, c = i & 31;
        xs[r*33+c] = xg[r*32+c];
    }
    for (int i = tid; i < 64*32; i += 256) {
        int r = i >> 5, c = i & 31;
        ts[r*33+c] = tg[r*32+c];
    }
    __syncthreads();
    if (tid < 192) {
        int r = (tid < 128) ? tid : (tid - 128);
        const float4* src = (tid < 128) ? (xs + r*33) : (ts + r*33);
        float s = 0.0f;
        #pragma unroll 8
        for (int c = 0; c < 32; c++) {
            float4 v = src[c];
            s += v.x*v.x + v.y*v.y + v.z*v.z + v.w*v.w;
        }
        if (tid < 128) xn2[r] = s; else tn2[r] = s;
    }
    __syncthreads();
    int tx = tid & 15, ty = tid >> 4;   // tx -> 4 m cols, ty -> 8 n rows
    float acc[8][4];
    #pragma unroll
    for (int i = 0; i < 8; i++)
        #pragma unroll
        for (int j = 0; j < 4; j++) acc[i][j] = 0.0f;
    #pragma unroll 2
    for (int k = 0; k < 32; k++) {
        float4 a[8], b[4];
        #pragma unroll
        for (int i = 0; i < 8; i++) a[i] = xs[(ty*8+i)*33 + k];
        #pragma unroll
        for (int j = 0; j < 4; j++) b[j] = ts[(tx*4+j)*33 + k];
        #pragma unroll
        for (int i = 0; i < 8; i++)
            #pragma unroll
            for (int j = 0; j < 4; j++)
                acc[i][j] = fmaf(a[i].x, b[j].x, fmaf(a[i].y, b[j].y,
                             fmaf(a[i].z, b[j].z, fmaf(a[i].w, b[j].w, acc[i][j]))));
    }
    #pragma unroll
    for (int i = 0; i < 8; i++) {
        int n = n0 + ty*8 + i;
        float xn = xn2[ty*8+i];
        float4 o;
        o.x = xn + tn2[tx*4+0] - 2.0f*acc[i][0];
        o.y = xn + tn2[tx*4+1] - 2.0f*acc[i][1];
        o.z = xn + tn2[tx*4+2] - 2.0f*acc[i][2];
        o.w = xn + tn2[tx*4+3] - 2.0f*acc[i][3];
        *(float4*)(g_XT + (size_t)n*TTe + m0 + tx*4) = o;
    }
}

// ======================= main kernel =======================
// smem layout (float offsets)
#define NB_O   0     // 17 int
#define RB_O   17    // 17 int (row bitmasks)
#define T1_O   36    // 17 float: raw popcount cnt[k]
#define M_O    64    // 16 * 272
#define KG_O   4416  // 16 * 272   Kt (swizzled) then aliased by G[k*16+m]
#define H_O    8768  // 16 * 272   H[j*16+l]
#define V_O    13120 // 16 * 16
#define SM_FLOATS 13376
#define SM_BYTES (SM_FLOATS*4)

__global__ __launch_bounds__(512, 2)
void ltfgw_kernel(const float* __restrict__ adj,
                  const int*   __restrict__ nbr,
                  const float* __restrict__ tmpl,
                  float* __restrict__ out) {
    extern __shared__ float smf[];
    int*   nb  = (int*)(smf + NB_O);
    int*   rbs = (int*)(smf + RB_O);
    float* t1f = smf + T1_O;

    const int n    = blockIdx.x;
    const int tid  = threadIdx.x;
    const int lane = tid & 31;
    const int t    = tid >> 5;
    const int l    = lane & 15;
    const int h    = lane >> 4;

    float* Mw  = smf + M_O  + t*272;
    float* KGw = smf + KG_O + t*272;   // Kt (swizzled float4 rows), later G
    float* Hw  = smf + H_O  + t*272;
    float* vsm = smf + V_O  + t*16;

    // ---- Phase A1: neighbor list ----
    if (tid < K1) nb[tid] = (tid == 0) ? n : nbr[n*Kn + tid - 1];
    __syncthreads();

    // ---- Phase A3 (parallel across warps): row bitmasks of binary 17x17 C1 ----
    {
        const float* arow = adj + (size_t)nb[t]*Nn;
        float v = (lane < K1) ? arow[nb[lane]] : 0.0f;
        unsigned bits = __ballot_sync(0xffffffffu, v != 0.0f);
        if (lane == 0) {
            rbs[t] = (int)bits;
            t1f[t] = (float)__popc(bits);   // raw count; alpha folded below
        }
        if (t == 0) {
            const float* arow2 = adj + (size_t)nb[16]*Nn;
            float v2 = (lane < K1) ? arow2[nb[lane]] : 0.0f;
            unsigned bits2 = __ballot_sync(0xffffffffu, v2 != 0.0f);
            if (lane == 0) {
                rbs[16] = (int)bits2;
                t1f[16] = (float)__popc(bits2);
            }
        }
    }

    // ---- Phase A2: M gather (per warp, LDG from precomputed XT) ----
    #pragma unroll
    for (int ii = 0; ii < 9; ii++) {
        int e = lane + 32*ii;
        if (e < 272) {
            int k = e >> 4;
            Mw[e] = __ldg(&g_XT[(size_t)nb[k]*TTe + t*16 + (e & 15)]);
        }
    }
    __syncthreads();

    const float alpha = g_alpha[0];
    const float oneMa = g_alpha[1];
    const float twoA  = 2.0f*alpha;
    const float apc   = alpha * PINV;

    // each warp derives the union mask locally
    unsigned rb_l = (lane < K1) ? (unsigned)rbs[lane] : 0u;
    const unsigned UB = __ballot_sync(0xffffffffu, rb_l != 0u);
    const int lastOuter = (UB == 0u) ? 1 : 3;

    const float qreg   = __ldg(&g_q[t*16 + l]);
    const float ac     = alpha * __ldg(&g_cq2[t*16 + l]);
    const float lanec2 = apc * (-2.0f * __ldg(&g_qc2[t*16 + l]));  // apc*(lanec-1)

    // ---- fold affine constants into M once: Mb = oneMa*M + ac + apc*cnt[k] ----
    #pragma unroll
    for (int ii = 0; ii < 9; ii++) {
        int e = lane + 32*ii;
        if (e < 272) {
            int k = e >> 4;
            Mw[e] = fmaf(oneMa, Mw[e], fmaf(apc, t1f[k], ac));
        }
    }
    __syncwarp();

    float karr[9];   // K parity layout: karr[ii] = K[2ii+h][l]
    float urow[9];   // urow[ii] = u_{2ii+h}
    float vreg = 1.0f;
    const int swz = (lane >> 1) & 3;   // Kt row-load swizzle for lane==k

    for (int outer = 0; ; outer++) {
        float ge[9];
        // ---------- grad ----------
        if (outer == 0 || UB == 0u) {
            // analytic H0: ge = Mb + cnt[k]*apc*(lanec-1)
            #pragma unroll
            for (int ii = 0; ii < 9; ii++) {
                int e = lane + 32*ii;
                ge[ii] = (e < 272) ? fmaf(t1f[e >> 4], lanec2, Mw[e]) : 0.0f;
            }
        } else {
            #pragma unroll
            for (int ii = 0; ii < 9; ii++) {
                int e = lane + 32*ii;
                if (e < 272) {
                    int k = e >> 4;
                    int bits = rbs[k];
                    float s = 0.0f;
                    while (bits) {
                        int j = __ffs(bits) - 1;
                        bits &= bits - 1;
                        s += Hw[j*16 + l];
                    }
                    ge[ii] = fmaf(-twoA, s, Mw[e]);
                } else ge[ii] = 0.0f;
            }
        }

        if (outer == lastOuter) {
            float acc = 0.0f;
            #pragma unroll
            for (int ii = 0; ii < 9; ii++)
                acc = fmaf(ge[ii], karr[ii]*urow[ii]*vreg, acc);
            #pragma unroll
            for (int s2 = 16; s2 > 0; s2 >>= 1)
                acc += __shfl_xor_sync(0xffffffffu, acc, s2);
            if (lane == 0) out[n*Tt + t] = acc;
            break;
        }

        // ---------- eps via integer redux (order-isomorphic key) ----------
        float mn = ge[0], mx = ge[0];
        #pragma unroll
        for (int ii = 1; ii < 8; ii++) { mn = fminf(mn, ge[ii]); mx = fmaxf(mx, ge[ii]); }
        if (lane < 16) { mn = fminf(mn, ge[8]); mx = fmaxf(mx, ge[8]); }
        mn = key2f(redux_min_s32(f2key(mn)));
        mx = key2f(redux_max_s32(f2key(mx)));
        float inv_eps = __fdividef(1.0f, 0.1f*(mx - mn) + TINYF);

        // ---------- K = exp; store swizzled Kt ----------
        #pragma unroll
        for (int ii = 0; ii < 9; ii++) {
            int e = lane + 32*ii;
            if (e < 272) {
                float kv = __expf((mn - ge[ii]) * inv_eps);
                karr[ii] = kv;
                int k = 2*ii + h;
                KGw[k*16 + (((l>>2) ^ (ii&3))<<2) + (l&3)] = kv;
            } else karr[ii] = 0.0f;
        }
        __syncwarp();

        // ---------- load my row k=lane into registers (once per outer) ----------
        float4 kr0, kr1, kr2, kr3;
        if (lane < K1) {
            const float4* kt4 = (const float4*)KGw;
            kr0 = kt4[lane*4 + (0^swz)];
            kr1 = kt4[lane*4 + (1^swz)];
            kr2 = kt4[lane*4 + (2^swz)];
            kr3 = kt4[lane*4 + (3^swz)];
        } else {
            kr0 = kr1 = kr2 = kr3 = make_float4(0.f,0.f,0.f,0.f);
        }
        __syncwarp();   // Kt region free for G after this

        // ---------- Sinkhorn (proven register/smem form) ----------
        float u;
        {
            float s0 = (kr0.x + kr0.y) + (kr0.z + kr0.w);
            float s1 = (kr1.x + kr1.y) + (kr1.z + kr1.w);
            float s2 = (kr2.x + kr2.y) + (kr2.z + kr2.w);
            float s3 = (kr3.x + kr3.y) + (kr3.z + kr3.w);
            float S  = (s0 + s1) + (s2 + s3);
            if (lane >= K1) S = 1.0f;
            u = __fdividef(PINV, fmaxf(S, TINYF));
        }
        #pragma unroll
        for (int it = 0; it < 5; it++) {
            // gather u into parity layout
            #pragma unroll
            for (int ii = 0; ii < 9; ii++)
                urow[ii] = __shfl_sync(0xffffffffu, u, 2*ii + h);
            // v-step: 3-accumulator column partials + xor16
            float a0 = karr[0]*urow[0];
            float a1 = karr[1]*urow[1];
            float a2 = karr[2]*urow[2];
            a0 = fmaf(karr[3], urow[3], a0);
            a1 = fmaf(karr[4], urow[4], a1);
            a2 = fmaf(karr[5], urow[5], a2);
            a0 = fmaf(karr[6], urow[6], a0);
            a1 = fmaf(karr[7], urow[7], a1);
            a2 = fmaf(karr[8], urow[8], a2);
            float sv = (a0 + a1) + a2;
            sv += __shfl_xor_sync(0xffffffffu, sv, 16);
            vreg = __fdividef(qreg, fmaxf(sv, TINYF));
            if (it == 4) break;
            // publish v to smem, register-local u-step (row regs x v broadcast)
            if (lane < 16) vsm[lane] = vreg;
            __syncwarp();
            {
                const float4* vv4 = (const float4*)vsm;
                float4 v0 = vv4[0], v1 = vv4[1], v2 = vv4[2], v3 = vv4[3];
                float b0 = kr0.x*v0.x, b1 = kr0.y*v0.y, b2 = kr0.z*v0.z, b3 = kr0.w*v0.w;
                b0 = fmaf(kr1.x, v1.x, b0); b1 = fmaf(kr1.y, v1.y, b1);
                b2 = fmaf(kr1.z, v1.z, b2); b3 = fmaf(kr1.w, v1.w, b3);
                b0 = fmaf(kr2.x, v2.x, b0); b1 = fmaf(kr2.y, v2.y, b1);
                b2 = fmaf(kr2.z, v2.z, b2); b3 = fmaf(kr2.w, v2.w, b3);
                b0 = fmaf(kr3.x, v3.x, b0); b1 = fmaf(kr3.y, v3.y, b1);
                b2 = fmaf(kr3.z, v3.z, b2); b3 = fmaf(kr3.w, v3.w, b3);
                float S = (b0 + b1) + (b2 + b3);
                if (lane >= K1) S = 1.0f;
                u = __fdividef(PINV, fmaxf(S, TINYF));
            }
        }

        // ---------- G to smem (aliases Kt) + H build (half-warp j pairs) ----------
        if (UB) {
            #pragma unroll
            for (int ii = 0; ii < 9; ii++) {
                int e = lane + 32*ii;
                if (e < 272) KGw[e] = karr[ii]*urow[ii]*vreg;  // conflict-free
            }
            __syncwarp();
            const float4* tp = (const float4*)(tmpl + (t*16 + l)*16);
            float4 c0 = __ldg(tp+0), c1 = __ldg(tp+1), c2 = __ldg(tp+2), c3 = __ldg(tp+3);
            unsigned ub = UB;
            while (ub) {
                int j0 = __ffs(ub) - 1; ub &= ub - 1u;
                int j1 = j0;
                bool have2 = (ub != 0u);
                if (have2) { j1 = __ffs(ub) - 1; ub &= ub - 1u; }
                int j = h ? j1 : j0;               // halves handle different rows
                const float4* gr = (const float4*)(KGw + j*16);
                float4 a = gr[0], b = gr[1], c = gr[2], d = gr[3];
                float p0 = a.x*c0.x, p1 = a.y*c0.y, p2 = a.z*c0.z, p3 = a.w*c0.w;
                p0 = fmaf(b.x, c1.x, p0); p1 = fmaf(b.y, c1.y, p1);
                p2 = fmaf(b.z, c1.z, p2); p3 = fmaf(b.w, c1.w, p3);
                p0 = fmaf(c.x, c2.x, p0); p1 = fmaf(c.y, c2.y, p1);
                p2 = fmaf(c.z, c2.z, p2); p3 = fmaf(c.w, c2.w, p3);
                p0 = fmaf(d.x, c3.x, p0); p1 = fmaf(d.y, c3.y, p1);
                p2 = fmaf(d.z, c3.z, p2); p3 = fmaf(d.w, c3.w, p3);
                float s = (p0 + p1) + (p2 + p3);
                if (h == 0 || have2) Hw[j*16 + l] = s;   // both halves write their row
            }
            __syncwarp();
        }
    }
}

extern "C" void kernel_launch(void* const* d_in, const int* in_sizes, int n_in,
                              void* d_out, int out_size) {
    const float* x    = (const float*)d_in[0];
    const float* adj  = (const float*)d_in[1];
    const int*   nbr  = (const int*)  d_in[2];
    const float* tmpl = (const float*)d_in[3];
    const float* tf   = (const float*)d_in[4];
    const float* q0   = (const float*)d_in[5];
    const float* a0   = (const float*)d_in[6];
    float* out = (float*)d_out;

    cudaFuncSetAttribute(prep_kernel,  cudaFuncAttributeMaxDynamicSharedMemorySize, GSM_BYTES);
    cudaFuncSetAttribute(ltfgw_kernel, cudaFuncAttributeMaxDynamicSharedMemorySize, SM_BYTES);

    prep_kernel<<<129, 256, GSM_BYTES>>>(x, tf, q0, tmpl, a0);
    ltfgw_kernel<<<Nn, 512, SM_BYTES>>>(adj, nbr, tmpl, out);
    (void)in_sizes; (void)n_in; (void)out_size;
}